// round 3
// baseline (speedup 1.0000x reference)
#include <cuda_runtime.h>
#include <cuda_bf16.h>
#include <math.h>

// Problem constants
#define NB   16
#define CI   64
#define CO   128
#define HH   256
#define WW   256
#define KK   576          // CI*3*3

// Tile config
#define CO_TILE 32
#define H_TILE  8
#define W_TILE  32
#define X_ROWS  (H_TILE + 2)      // 10
#define X_COLS  34                // W_TILE + 2
#define X_STRIDE 36               // padded: row stride 144B (16B-aligned)
#define THREADS 256

typedef unsigned long long u64;
typedef unsigned int       u32;

// Scratch: transformed weights laid out [k][co]  (k = ci*9 + kh*3 + kw)
__device__ float g_wt[KK * CO];

__global__ void nac_weight_transform(const float* __restrict__ Wh,
                                     const float* __restrict__ Mh) {
    int i = blockIdx.x * 256 + threadIdx.x;         // over CO*KK
    if (i < CO * KK) {
        int co = i / KK;
        int k  = i - co * KK;
        float w = tanhf(Wh[i]);
        float m = 1.0f / (1.0f + expf(-Mh[i]));
        g_wt[k * CO + co] = w * m;
    }
}

// packed-pair helpers (sm_100+ f32x2 pipe)
__device__ __forceinline__ u64 dup_f32x2(u32 v) {
    u64 d;
    asm("mov.b64 %0, {%1, %1};" : "=l"(d) : "r"(v));
    return d;
}
__device__ __forceinline__ void fma_f32x2(u64& acc, u64 w, u64 x) {
    asm("fma.rn.f32x2 %0, %1, %2, %0;" : "+l"(acc) : "l"(w), "l"(x));
}

__global__ __launch_bounds__(THREADS, 1)
void conv_nac_kernel(const float* __restrict__ x, float* __restrict__ out) {
    extern __shared__ float smem[];
    float* sx = smem;                               // [CI][X_ROWS][X_STRIDE]
    float* sw = smem + CI * X_ROWS * X_STRIDE;      // [CI*9][CO_TILE]

    const int tid = threadIdx.x;

    // Tile coordinates
    const int wt  = blockIdx.x & 7;                 // 8 w-tiles
    const int ht  = blockIdx.x >> 3;                // 32 h-tiles
    const int co0 = blockIdx.y * CO_TILE;
    const int n   = blockIdx.z;
    const int h0  = ht * H_TILE;
    const int w0  = wt * W_TILE;

    // ---- Stage weights: sw[k][c] = g_wt[k][co0+c] ----
    {
        const int n4 = (CI * 9 * CO_TILE) / 4;      // 4608 float4s
        const float4* gw4 = reinterpret_cast<const float4*>(g_wt);
        float4* sw4 = reinterpret_cast<float4*>(sw);
        #pragma unroll 4
        for (int e = tid; e < n4; e += THREADS) {
            int k  = e >> 3;                        // e / (CO_TILE/4)
            int c4 = e & 7;
            sw4[e] = gw4[k * (CO / 4) + (co0 >> 2) + c4];
        }
    }

    // ---- Stage input halo tile: sx[ci][r][c], r in [h0-1,h0+8], c in [w0-1,w0+32] ----
    {
        const float* xb = x + (size_t)n * CI * HH * WW;
        const int total = CI * X_ROWS * X_COLS;     // 21760
        #pragma unroll 4
        for (int idx = tid; idx < total; idx += THREADS) {
            int c  = idx % X_COLS;
            int t  = idx / X_COLS;
            int r  = t % X_ROWS;
            int ci = t / X_ROWS;
            int gh = h0 - 1 + r;
            int gw = w0 - 1 + c;
            float v = 0.0f;
            if ((unsigned)gh < HH && (unsigned)gw < WW)
                v = xb[((size_t)ci * HH + gh) * WW + gw];
            sx[(ci * X_ROWS + r) * X_STRIDE + c] = v;
        }
    }
    __syncthreads();

    // ---- Compute: thread -> 8 co (as 4 f32x2 pairs) x 4 px ----
    const int co_g = tid >> 6;                      // 0..3 (co sub-block of 8)
    const int pix  = tid & 63;
    const int ph   = pix >> 3;                      // 0..7
    const int pw   = (pix & 7) << 2;                // 0,4,...,28

    u64 acc[4][4];                                  // [co-pair][px]
    #pragma unroll
    for (int c = 0; c < 4; c++)
        #pragma unroll
        for (int p = 0; p < 4; p++) acc[c][p] = 0ULL;

    const u32* sxu = reinterpret_cast<const u32*>(sx);

    #pragma unroll 1
    for (int ci = 0; ci < CI; ci++) {
        // byte-exact base of this thread's 8-co slab for current ci (u64 units)
        const u64* swc = reinterpret_cast<const u64*>(sw) +
                         ((ci * 9 * CO_TILE + co_g * 8) >> 1);
        #pragma unroll
        for (int kh = 0; kh < 3; kh++) {
            // 6 x-values for this (ci, row), duplicated into both pair-halves
            const u32* xr = sxu + (ci * X_ROWS + ph + kh) * X_STRIDE + pw;
            uint4 xa = *reinterpret_cast<const uint4*>(xr);
            uint2 xb = *reinterpret_cast<const uint2*>(xr + 4);
            u64 xd[6];
            xd[0] = dup_f32x2(xa.x); xd[1] = dup_f32x2(xa.y);
            xd[2] = dup_f32x2(xa.z); xd[3] = dup_f32x2(xa.w);
            xd[4] = dup_f32x2(xb.x); xd[5] = dup_f32x2(xb.y);
            #pragma unroll
            for (int kw = 0; kw < 3; kw++) {
                // 4 weight pairs (8 consecutive co) via two LDS.128
                const u64* wr = swc + (kh * 3 + kw) * (CO_TILE / 2);
                ulonglong2 wA = *reinterpret_cast<const ulonglong2*>(wr);
                ulonglong2 wB = *reinterpret_cast<const ulonglong2*>(wr + 2);
                #pragma unroll
                for (int p = 0; p < 4; p++) {
                    fma_f32x2(acc[0][p], wA.x, xd[kw + p]);
                    fma_f32x2(acc[1][p], wA.y, xd[kw + p]);
                    fma_f32x2(acc[2][p], wB.x, xd[kw + p]);
                    fma_f32x2(acc[3][p], wB.y, xd[kw + p]);
                }
            }
        }
    }

    // ---- Epilogue: unpack pairs, store float4 per co plane ----
    float* ob = out + (((size_t)n * CO + co0 + co_g * 8) * HH + h0 + ph) * WW + w0 + pw;
    #pragma unroll
    for (int c = 0; c < 4; c++) {
        float lo[4], hi[4];
        #pragma unroll
        for (int p = 0; p < 4; p++) {
            u32 l, h;
            asm("mov.b64 {%0, %1}, %2;" : "=r"(l), "=r"(h) : "l"(acc[c][p]));
            lo[p] = __uint_as_float(l);
            hi[p] = __uint_as_float(h);
        }
        float* o0 = ob + (size_t)(2 * c) * HH * WW;
        float* o1 = ob + (size_t)(2 * c + 1) * HH * WW;
        *reinterpret_cast<float4*>(o0) = make_float4(lo[0], lo[1], lo[2], lo[3]);
        *reinterpret_cast<float4*>(o1) = make_float4(hi[0], hi[1], hi[2], hi[3]);
    }
}

extern "C" void kernel_launch(void* const* d_in, const int* in_sizes, int n_in,
                              void* d_out, int out_size) {
    const float* x  = (const float*)d_in[0];
    const float* Wh = (const float*)d_in[1];
    const float* Mh = (const float*)d_in[2];
    float* out = (float*)d_out;

    // 1) NAC weight transform (+ transpose to [k][co])
    nac_weight_transform<<<(CO * KK + 255) / 256, 256>>>(Wh, Mh);

    // 2) Tiled direct conv
    const int smem_bytes = (CI * X_ROWS * X_STRIDE + CI * 9 * CO_TILE) * sizeof(float);
    cudaFuncSetAttribute(conv_nac_kernel,
                         cudaFuncAttributeMaxDynamicSharedMemorySize, smem_bytes);
    dim3 grid((WW / W_TILE) * (HH / H_TILE), CO / CO_TILE, NB);
    conv_nac_kernel<<<grid, THREADS, smem_bytes>>>(x, out);
}

// round 6
// speedup vs baseline: 2.9633x; 2.9633x over previous
#include <cuda_runtime.h>
#include <cuda_bf16.h>
#include <math.h>
#include <stdint.h>

// ---------------- problem constants ----------------
#define NB   16
#define CIN  64
#define COUT 128
#define HH   256
#define WW   256

#define THREADS 256

// smem row stride: 64 ci * 2B = 128B data, padded to 144B (conflict-free ldmatrix)
#define RSTRIDE 144
// plane offsets (bytes)
#define XHI 0u
#define XLO 18432u
#define WHI 36864u
#define WLO 55296u
#define SMEM_BYTES 73728

// global scratch: bf16 weights, padded rows: [plane][tap][co][72]
__device__ __align__(16) __nv_bfloat16 g_wt[2 * 9 * 128 * 72];

__global__ void nac_weight_transform(const float* __restrict__ Wh,
                                     const float* __restrict__ Mh) {
    int i = blockIdx.x * 256 + threadIdx.x;       // over CO*576
    if (i >= COUT * 576) return;
    int co = i / 576, k = i % 576;
    int ci = k / 9, s = k % 9;                    // k = ci*9 + (kh*3+kw)
    float w = tanhf(Wh[i]) * (1.0f / (1.0f + expf(-Mh[i])));
    __nv_bfloat16 hi = __float2bfloat16_rn(w);
    __nv_bfloat16 lo = __float2bfloat16_rn(w - __bfloat162float(hi));
    g_wt[((0 * 9 + s) * 128 + co) * 72 + ci] = hi;
    g_wt[((1 * 9 + s) * 128 + co) * 72 + ci] = lo;
}

__device__ __forceinline__ uint32_t smem_u32(const void* p) {
    uint32_t a;
    asm("{ .reg .u64 t; cvta.to.shared.u64 t, %1; cvt.u32.u64 %0, t; }" : "=r"(a) : "l"(p));
    return a;
}

__device__ __forceinline__ void ldsm_x4(uint32_t& r0, uint32_t& r1, uint32_t& r2,
                                        uint32_t& r3, uint32_t addr) {
    asm volatile("ldmatrix.sync.aligned.m8n8.x4.shared.b16 {%0,%1,%2,%3}, [%4];"
                 : "=r"(r0), "=r"(r1), "=r"(r2), "=r"(r3) : "r"(addr));
}

__device__ __forceinline__ void mma16816(float* d, uint32_t a0, uint32_t a1,
                                         uint32_t a2, uint32_t a3,
                                         uint32_t b0, uint32_t b1) {
    asm volatile(
        "mma.sync.aligned.m16n8k16.row.col.f32.bf16.bf16.f32 "
        "{%0,%1,%2,%3}, {%4,%5,%6,%7}, {%8,%9}, {%0,%1,%2,%3};"
        : "+f"(d[0]), "+f"(d[1]), "+f"(d[2]), "+f"(d[3])
        : "r"(a0), "r"(a1), "r"(a2), "r"(a3), "r"(b0), "r"(b1));
}

__global__ __launch_bounds__(THREADS, 2)
void conv_mma_kernel(const float* __restrict__ x, float* __restrict__ out) {
    __shared__ __align__(16) char smem[SMEM_BYTES];
    const uint32_t sb = smem_u32(smem);

    const int tid  = threadIdx.x;
    const int warp = tid >> 5;
    const int lane = tid & 31;

    const int n  = blockIdx.z;
    const int h0 = blockIdx.y * 2;
    const int w0 = blockIdx.x * 64;

    // warp tiling: 4 co-groups x 2 pix-groups
    const int cg = warp >> 1;                     // 0..3 -> co base cg*32
    const int pg = warp & 1;                      // 0..1 -> pix base pg*64 (h row)

    // ldmatrix lane address bases (within plane)
    // A (W): mat = lane/8: row = (lane&7) + ((lane>>3)&1)*8, colB = (lane>>4)*16
    const uint32_t a_base = sb +
        (uint32_t)((cg * 32 + (lane & 7) + ((lane >> 3) & 1) * 8) * RSTRIDE) +
        (uint32_t)((lane >> 4) * 16);
    // B (X): row = pix0 + (lane&7) + (lane>>4)*8, colB = ((lane>>3)&1)*16
    const uint32_t b_base = sb +
        (uint32_t)((pg * 64 + (lane & 7) + (lane >> 4) * 8) * RSTRIDE) +
        (uint32_t)(((lane >> 3) & 1) * 16);

    // build-phase mapping: wl = tid&63, grp = tid>>6 -> hl = grp&1, ci half = grp>>1
    const int wl = tid & 63;
    const int hl = (tid >> 6) & 1;
    const int ch = (tid >> 7) * 32;               // ci base 0 or 32
    const float* xb = x + (size_t)n * CIN * HH * WW;

    float acc[2][8][4];
    #pragma unroll
    for (int mi = 0; mi < 2; mi++)
        #pragma unroll
        for (int ni = 0; ni < 8; ni++)
            #pragma unroll
            for (int e = 0; e < 4; e++) acc[mi][ni][e] = 0.0f;

    const uint32_t aoffs[3] = {WHI, WHI, WLO};
    const uint32_t boffs[3] = {XHI, XLO, XHI};

    #pragma unroll 1
    for (int it = 0; it < 9; it++) {
        const int kh = it / 3, kw = it % 3;
        __syncthreads();                          // smem free from previous tap

        // ---- stage W slabs (linear copy, padded rows already in g_wt) ----
        {
            const uint4* s0 = (const uint4*)((const char*)g_wt + (size_t)it * 18432);
            const uint4* s1 = (const uint4*)((const char*)g_wt + (size_t)(9 + it) * 18432);
            uint4* d0 = (uint4*)(smem + WHI);
            uint4* d1 = (uint4*)(smem + WLO);
            #pragma unroll
            for (int e = tid; e < 1152; e += THREADS) { d0[e] = s0[e]; d1[e] = s1[e]; }
        }

        // ---- build X tile: row p = hl*64+wl, cols = 32 ci (hi/lo planes) ----
        {
            const int gh = h0 + hl + kh - 1;
            const int gw = w0 + wl + kw - 1;
            const bool inb = ((unsigned)gh < HH) && ((unsigned)gw < WW);
            const float* xp = xb + ((size_t)ch * HH + gh) * WW + gw;
            char* rowh = smem + XHI + (hl * 64 + wl) * RSTRIDE + ch * 2;
            char* rowl = smem + XLO + (hl * 64 + wl) * RSTRIDE + ch * 2;
            #pragma unroll
            for (int c8 = 0; c8 < 4; c8++) {      // 4 chunks of 8 ci
                float v[8];
                #pragma unroll
                for (int j = 0; j < 8; j++)
                    v[j] = inb ? xp[(size_t)(c8 * 8 + j) * (HH * WW)] : 0.0f;
                uint32_t hp[4], lp[4];
                #pragma unroll
                for (int j = 0; j < 4; j++) {
                    __nv_bfloat162 h2 = __floats2bfloat162_rn(v[2 * j], v[2 * j + 1]);
                    float rl0 = v[2 * j]     - __bfloat162float(h2.x);
                    float rl1 = v[2 * j + 1] - __bfloat162float(h2.y);
                    __nv_bfloat162 l2 = __floats2bfloat162_rn(rl0, rl1);
                    hp[j] = *(uint32_t*)&h2;
                    lp[j] = *(uint32_t*)&l2;
                }
                *(uint4*)(rowh + c8 * 16) = make_uint4(hp[0], hp[1], hp[2], hp[3]);
                *(uint4*)(rowl + c8 * 16) = make_uint4(lp[0], lp[1], lp[2], lp[3]);
            }
        }
        __syncthreads();

        // ---- compute: 3 bf16-split passes over K=64 ----
        #pragma unroll 1
        for (int pass = 0; pass < 3; pass++) {
            const uint32_t ab = a_base + aoffs[pass];
            const uint32_t bb = b_base + boffs[pass];
            #pragma unroll
            for (int k = 0; k < 4; k++) {
                uint32_t a0[4], a1[4];
                ldsm_x4(a0[0], a0[1], a0[2], a0[3], ab + k * 32);
                ldsm_x4(a1[0], a1[1], a1[2], a1[3], ab + 2304 + k * 32); // +16 rows
                uint32_t bf[4][4];
                #pragma unroll
                for (int np = 0; np < 4; np++)
                    ldsm_x4(bf[np][0], bf[np][1], bf[np][2], bf[np][3],
                            bb + np * 2304 + k * 32);                    // +16 pix rows
                #pragma unroll
                for (int ni = 0; ni < 8; ni++) {
                    uint32_t b0 = bf[ni >> 1][(ni & 1) * 2];
                    uint32_t b1 = bf[ni >> 1][(ni & 1) * 2 + 1];
                    mma16816(acc[0][ni], a0[0], a0[1], a0[2], a0[3], b0, b1);
                    mma16816(acc[1][ni], a1[0], a1[1], a1[2], a1[3], b0, b1);
                }
            }
        }
    }

    // ---- epilogue: direct register stores (32B-sector coalesced) ----
    const int gh = h0 + pg;
    const int qr = lane >> 2;                     // row within m8
    const int qc = 2 * (lane & 3);                // col pair within n8
    #pragma unroll
    for (int mi = 0; mi < 2; mi++) {
        const int co_r = cg * 32 + mi * 16 + qr;
        float* ob = out + (((size_t)n * COUT + co_r) * HH + gh) * WW + w0;
        float* ob8 = ob + (size_t)8 * HH * WW;    // co_r + 8
        #pragma unroll
        for (int ni = 0; ni < 8; ni++) {
            *(float2*)(ob  + ni * 8 + qc) = make_float2(acc[mi][ni][0], acc[mi][ni][1]);
            *(float2*)(ob8 + ni * 8 + qc) = make_float2(acc[mi][ni][2], acc[mi][ni][3]);
        }
    }
}

extern "C" void kernel_launch(void* const* d_in, const int* in_sizes, int n_in,
                              void* d_out, int out_size) {
    const float* x  = (const float*)d_in[0];
    const float* Wh = (const float*)d_in[1];
    const float* Mh = (const float*)d_in[2];
    float* out = (float*)d_out;

    nac_weight_transform<<<(COUT * 576 + 255) / 256, 256>>>(Wh, Mh);

    dim3 grid(WW / 64, HH / 2, NB);               // 4 x 128 x 16 = 8192 CTAs
    conv_mma_kernel<<<grid, THREADS>>>(x, out);
}